// round 1
// baseline (speedup 1.0000x reference)
#include <cuda_runtime.h>
#include <cstddef>

#define D_IN  128
#define D_HID 128
#define D_OUT 32
#define NMAX  100000

// ---------------- static device scratch (no runtime allocation) ----------------
__device__ float  g_agg1[(size_t)NMAX * D_HID];   // 51.2 MB
__device__ float  g_h1  [(size_t)NMAX * D_HID];   // 51.2 MB (pre-BN then post-BN in place)
__device__ float  g_tr  [(size_t)NMAX * 64];      // [t | r2] = h1 @ [W_rel2 | W_root2]
__device__ float  g_agg2[(size_t)NMAX * D_OUT];   // agg2 then h2pre in place
__device__ double g_stats[320];                   // sum1[128] sq1[128] sum2[32] sq2[32]
__device__ float  g_ss[320];                      // scale1[128] shift1[128] scale2[32] shift2[32]
__device__ float  g_wcat2[128 * 64];              // [W_rel2 | W_root2] column-concat
__device__ int    g_is64;

// ---------------- small utility kernels ----------------
__global__ void zero4_kernel(float* p, int n4) {
    int i = blockIdx.x * blockDim.x + threadIdx.x;
    int stride = gridDim.x * blockDim.x;
    float4 z = make_float4(0.f, 0.f, 0.f, 0.f);
    for (; i < n4; i += stride) ((float4*)p)[i] = z;
}

__global__ void zero_d_kernel(double* p, int n) {
    int i = blockIdx.x * blockDim.x + threadIdx.x;
    if (i < n) p[i] = 0.0;
}

// Detect whether edge_index buffer is int64 (odd 32-bit words all zero) or int32.
__global__ void detect_kernel(const int* ei, int E) {
    if (threadIdx.x != 0 || blockIdx.x != 0) return;
    int n = 2 * E;
    int allzero = 1;
    for (int k = 1; k < 256 && k < n; k += 2) {
        if (ei[k] != 0) { allzero = 0; break; }
    }
    g_is64 = allzero;
}

// Build column-concat [W_rel2 | W_root2] : [128][64]
__global__ void prep_w_kernel(const float* __restrict__ Wrel2,
                              const float* __restrict__ Wroot2,
                              float* __restrict__ wcat2) {
    int i = blockIdx.x * blockDim.x + threadIdx.x;
    if (i < 128 * 64) {
        int r = i >> 6, c = i & 63;
        wcat2[i] = (c < 32) ? Wrel2[r * 32 + c] : Wroot2[r * 32 + (c - 32)];
    }
}

// ---------------- edge scatter: agg[dst] += feat[src] (vectorized L2 reductions) ----------------
template <int LANES>  // LANES * 4 floats per edge row
__global__ void __launch_bounds__(256) scatter_kernel(
    const float* __restrict__ feat, int featStride,
    const void* __restrict__ eiv, int E,
    float* __restrict__ agg, int aggStride)
{
    int gid = blockIdx.x * 256 + threadIdx.x;
    int e = gid / LANES;
    bool valid = (e < E);
    int lane = threadIdx.x & 31;
    int j = lane & (LANES - 1);
    int grp = lane - j;

    int s = 0, d = 0;
    if (valid && j == 0) {
        if (g_is64) {
            const long long* p = (const long long*)eiv;
            s = (int)p[e];
            d = (int)p[(size_t)E + e];
        } else {
            const int* p = (const int*)eiv;
            s = p[e];
            d = p[E + e];
        }
    }
    s = __shfl_sync(0xffffffffu, s, grp);
    d = __shfl_sync(0xffffffffu, d, grp);
    if (!valid) return;

    const float4 v = *(const float4*)(feat + (size_t)s * featStride + (j << 2));
    float* a = agg + (size_t)d * aggStride + (j << 2);
    asm volatile("red.global.add.v4.f32 [%0], {%1,%2,%3,%4};"
                 :: "l"(a), "f"(v.x), "f"(v.y), "f"(v.z), "f"(v.w)
                 : "memory");
}

// ---------------- tiled fp32 GEMM: C = Aa@Ba + Ab@Bb + bias ----------------
// A matrices: [M, Ka/Kb] row-major; B matrices: [K, BN] row-major (ld = BN).
template <int BN, int TN>
__global__ void __launch_bounds__(256) gemm_kernel(
    const float* __restrict__ Aa, const float* __restrict__ Ba, int Ka,
    const float* __restrict__ Ab, const float* __restrict__ Bb, int Kb,
    const float* __restrict__ bias, float* __restrict__ C, int M)
{
    constexpr int BM = 128, BK = 16, TM = 8;
    constexpr int NT = (BM / TM) * (BN / TN);  // 256
    __shared__ float As[BK][BM + 4];
    __shared__ float Bs[BK][BN];

    const int tid = threadIdx.x;
    const int tx = tid % (BN / TN);
    const int ty = tid / (BN / TN);
    const int m0 = blockIdx.x * BM;

    float acc[TM][TN];
#pragma unroll
    for (int i = 0; i < TM; i++)
#pragma unroll
        for (int j = 0; j < TN; j++) acc[i][j] = 0.f;

    const int K = Ka + Kb;
    for (int kc = 0; kc < K; kc += BK) {
        const float* A; const float* B; int lda, kloc;
        if (kc < Ka) { A = Aa; B = Ba; lda = Ka; kloc = kc; }
        else         { A = Ab; B = Bb; lda = Kb; kloc = kc - Ka; }

        // load A tile (BM x BK) transposed into As[k][m]
#pragma unroll
        for (int t = 0; t < (BM * BK) / (4 * NT); t++) {
            int v = tid + t * NT;
            int row = v >> 2;
            int c4 = (v & 3) << 2;
            float4 val = make_float4(0.f, 0.f, 0.f, 0.f);
            if (m0 + row < M)
                val = *(const float4*)(A + (size_t)(m0 + row) * lda + kloc + c4);
            As[c4 + 0][row] = val.x;
            As[c4 + 1][row] = val.y;
            As[c4 + 2][row] = val.z;
            As[c4 + 3][row] = val.w;
        }
        // load B tile (BK x BN)
#pragma unroll
        for (int t = 0; t < (BK * BN) / (4 * NT); t++) {
            int v = tid + t * NT;
            int kr = v / (BN / 4);
            int c4 = (v % (BN / 4)) << 2;
            *(float4*)&Bs[kr][c4] = *(const float4*)(B + (size_t)(kloc + kr) * BN + c4);
        }
        __syncthreads();

#pragma unroll
        for (int k = 0; k < BK; k++) {
            float a[TM], b[TN];
#pragma unroll
            for (int i = 0; i < TM; i += 4)
                *(float4*)&a[i] = *(const float4*)&As[k][ty * TM + i];
#pragma unroll
            for (int j = 0; j < TN; j += 4)
                *(float4*)&b[j] = *(const float4*)&Bs[k][tx * TN + j];
#pragma unroll
            for (int i = 0; i < TM; i++)
#pragma unroll
                for (int j = 0; j < TN; j++)
                    acc[i][j] = fmaf(a[i], b[j], acc[i][j]);
        }
        __syncthreads();
    }

    float bfr[TN];
#pragma unroll
    for (int j = 0; j < TN; j++) bfr[j] = bias ? bias[tx * TN + j] : 0.f;

#pragma unroll
    for (int i = 0; i < TM; i++) {
        int grow = m0 + ty * TM + i;
        if (grow < M) {
#pragma unroll
            for (int j = 0; j < TN; j += 4) {
                float4 v;
                v.x = acc[i][j + 0] + bfr[j + 0];
                v.y = acc[i][j + 1] + bfr[j + 1];
                v.z = acc[i][j + 2] + bfr[j + 2];
                v.w = acc[i][j + 3] + bfr[j + 3];
                *(float4*)(C + (size_t)grow * BN + tx * TN + j) = v;
            }
        }
    }
}

// ---------------- column stats (sum, sumsq) in double ----------------
__global__ void __launch_bounds__(256) stats_kernel(
    const float* __restrict__ h, long long n, int D,
    double* __restrict__ sum, double* __restrict__ sq)
{
    long long i = (long long)blockIdx.x * 256 + threadIdx.x;
    long long stride = (long long)gridDim.x * 256;
    double ls = 0.0, lq = 0.0;
    for (; i < n; i += stride) {
        float v = h[i];
        ls += v;
        lq += (double)v * v;
    }
    __shared__ double shA[256], shB[256];
    int tid = threadIdx.x;
    shA[tid] = ls; shB[tid] = lq;
    __syncthreads();
    for (int off = 128; off >= D; off >>= 1) {
        if (tid < off) { shA[tid] += shA[tid + off]; shB[tid] += shB[tid + off]; }
        __syncthreads();
    }
    if (tid < D) {
        atomicAdd(&sum[tid], shA[tid]);
        atomicAdd(&sq[tid], shB[tid]);
    }
}

// h2pre = agg2 + r2 + b_rel2 (in place into agg2) fused with column stats (D=32)
__global__ void __launch_bounds__(256) combine_stats_kernel(
    float* __restrict__ agg2, const float* __restrict__ tr,
    const float* __restrict__ b, long long n,
    double* __restrict__ sum, double* __restrict__ sq)
{
    long long i = (long long)blockIdx.x * 256 + threadIdx.x;
    long long stride = (long long)gridDim.x * 256;
    int col = (int)(i & 31);
    float bias = b[col];
    double ls = 0.0, lq = 0.0;
    for (; i < n; i += stride) {
        long long row = i >> 5;
        int c = (int)(i & 31);
        float v = agg2[i] + __ldg(&tr[row * 64 + 32 + c]) + bias;
        agg2[i] = v;
        ls += v;
        lq += (double)v * v;
    }
    __shared__ double shA[256], shB[256];
    int tid = threadIdx.x;
    shA[tid] = ls; shB[tid] = lq;
    __syncthreads();
    for (int off = 128; off >= 32; off >>= 1) {
        if (tid < off) { shA[tid] += shA[tid + off]; shB[tid] += shB[tid + off]; }
        __syncthreads();
    }
    if (tid < 32) {
        atomicAdd(&sum[tid], shA[tid]);
        atomicAdd(&sq[tid], shB[tid]);
    }
}

// per-column BN affine coefficients
__global__ void bn_finalize_kernel(
    const double* __restrict__ sum, const double* __restrict__ sq,
    const float* __restrict__ gamma, const float* __restrict__ beta,
    float* __restrict__ scale, float* __restrict__ shift, float invM)
{
    int c = threadIdx.x;
    double mu = sum[c] * (double)invM;
    double var = sq[c] * (double)invM - mu * mu;
    float s = gamma[c] * rsqrtf((float)var + 1e-5f);
    scale[c] = s;
    shift[c] = beta[c] - (float)mu * s;
}

__global__ void __launch_bounds__(256) bn_relu_kernel(
    const float* __restrict__ in, float* __restrict__ out, long long n, int mask,
    const float* __restrict__ scale, const float* __restrict__ shift)
{
    long long i = (long long)blockIdx.x * blockDim.x + threadIdx.x;
    long long stride = (long long)gridDim.x * blockDim.x;
    for (; i < n; i += stride) {
        int c = (int)(i & mask);
        float v = fmaf(in[i], __ldg(&scale[c]), __ldg(&shift[c]));
        out[i] = fmaxf(v, 0.f);
    }
}

static inline int ceil_div_i(int a, int b) { return (a + b - 1) / b; }

// ---------------- launch ----------------
extern "C" void kernel_launch(void* const* d_in, const int* in_sizes, int n_in,
                              void* d_out, int out_size)
{
    const float* x      = (const float*)d_in[0];
    const void*  ei     = d_in[1];
    const float* Wrel1  = (const float*)d_in[2];
    const float* brel1  = (const float*)d_in[3];
    const float* Wroot1 = (const float*)d_in[4];
    const float* gamma1 = (const float*)d_in[5];
    const float* beta1  = (const float*)d_in[6];
    const float* Wrel2  = (const float*)d_in[7];
    const float* brel2  = (const float*)d_in[8];
    const float* Wroot2 = (const float*)d_in[9];
    const float* gamma2 = (const float*)d_in[10];
    const float* beta2  = (const float*)d_in[11];

    const int N = in_sizes[0] / D_IN;
    const int E = in_sizes[1] / 2;

    float *agg1, *h1, *tr, *agg2, *ss, *wcat2;
    double* stats;
    cudaGetSymbolAddress((void**)&agg1, g_agg1);
    cudaGetSymbolAddress((void**)&h1, g_h1);
    cudaGetSymbolAddress((void**)&tr, g_tr);
    cudaGetSymbolAddress((void**)&agg2, g_agg2);
    cudaGetSymbolAddress((void**)&stats, g_stats);
    cudaGetSymbolAddress((void**)&ss, g_ss);
    cudaGetSymbolAddress((void**)&wcat2, g_wcat2);

    detect_kernel<<<1, 32>>>((const int*)ei, E);
    zero4_kernel<<<2048, 256>>>(agg1, N * D_HID / 4);
    zero4_kernel<<<512, 256>>>(agg2, N * D_OUT / 4);
    zero_d_kernel<<<2, 256>>>(stats, 320);
    prep_w_kernel<<<32, 256>>>(Wrel2, Wroot2, wcat2);

    // Layer 1: aggregate x in 128-d, then [agg1|x] @ [W_rel1;W_root1] + b_rel1
    {
        long long t = (long long)E * 32;
        int blocks = (int)((t + 255) / 256);
        scatter_kernel<32><<<blocks, 256>>>(x, D_IN, ei, E, agg1, D_HID);
    }
    gemm_kernel<128, 8><<<ceil_div_i(N, 128), 256>>>(
        agg1, Wrel1, D_HID, x, Wroot1, D_IN, brel1, h1, N);

    stats_kernel<<<512, 256>>>(h1, (long long)N * D_HID, D_HID, stats, stats + 128);
    bn_finalize_kernel<<<1, 128>>>(stats, stats + 128, gamma1, beta1, ss, ss + 128, 1.0f / (float)N);
    bn_relu_kernel<<<2048, 256>>>(h1, h1, (long long)N * D_HID, D_HID - 1, ss, ss + 128);

    // Layer 2: project FIRST (t = h1@W_rel2, r2 = h1@W_root2), then scatter t in 32-d
    gemm_kernel<64, 4><<<ceil_div_i(N, 128), 256>>>(
        h1, wcat2, D_HID, nullptr, nullptr, 0, nullptr, tr, N);
    {
        long long t = (long long)E * 8;
        int blocks = (int)((t + 255) / 256);
        scatter_kernel<8><<<blocks, 256>>>(tr, 64, ei, E, agg2, D_OUT);
    }
    combine_stats_kernel<<<512, 256>>>(agg2, tr, brel2, (long long)N * D_OUT,
                                       stats + 256, stats + 288);
    bn_finalize_kernel<<<1, 32>>>(stats + 256, stats + 288, gamma2, beta2,
                                  ss + 256, ss + 288, 1.0f / (float)N);
    bn_relu_kernel<<<1024, 256>>>(agg2, (float*)d_out, (long long)N * D_OUT, D_OUT - 1,
                                  ss + 256, ss + 288);
}